// round 9
// baseline (speedup 1.0000x reference)
#include <cuda_runtime.h>
#include <math.h>
#include <float.h>

static constexpr int BATCH = 2;
static constexpr int T     = 2048;
static constexpr int BT    = BATCH * T;      // 4096
static constexpr int D     = 512;
static constexpr int H     = 8;
static constexpr int DH    = 64;
static constexpr int NL    = 4;
static constexpr int FF    = 2048;
static constexpr int V     = 32000;
static constexpr int SLOTS = 32768;
static constexpr int TOPK  = 8;

// ---------------- scratch (single __device__ array, carved by offsets) ----------------
static constexpr long OFF_X  = 0;
static constexpr long OFF_Q  = OFF_X  + (long)BT * D;
static constexpr long OFF_K  = OFF_Q  + (long)BT * D;
static constexpr long OFF_V  = OFF_K  + (long)BT * D;
static constexpr long OFF_AO = OFF_V  + (long)BT * D;
static constexpr long OFF_MQ = OFF_AO + (long)BT * D;
static constexpr long OFF_RD = OFF_MQ + (long)BT * D;
static constexpr long OFF_HH = OFF_RD + (long)BT * D;
static constexpr long OFF_SC = OFF_HH + (long)BT * FF;
static constexpr long OFF_MS = OFF_SC + (long)BATCH * H * T * T;
static constexpr long SCRATCH_TOTAL = OFF_MS + (long)BT * SLOTS;   // ~224.4M floats

__device__ float g_scratch[SCRATCH_TOTAL];

__device__ __forceinline__ float gelu_f(float x) {
    float x3 = x * x * x;
    return 0.5f * x * (1.0f + tanhf(0.7978845608028654f * (x + 0.044715f * x3)));
}

enum { EPI_NONE = 0, EPI_BIAS = 1, EPI_BIAS_RES = 2, EPI_BIAS_GELU = 3 };

// ---------------- general tiled SGEMM ----------------
// C[M,N] = alpha * A[M,K] @ op(B) (+bias[n]) (+gelu) (+res), op(B)=B^T when TB
// Batched via blockIdx.z: offset = (z/bdiv)*s1 + (z%bdiv)*s2 for A, B, C (res uses C's).
// REQUIRES: M % BM == 0, N % BN == 0, K % 8 == 0  (verified for every call site).
template<int BM, int BN, bool TB, int EPI>
__global__ __launch_bounds__((BM/8)*(BN/8))
void sgemm_k(int M, int N, int K,
             const float* __restrict__ A, int lda, long sA1, long sA2,
             const float* __restrict__ Bp, int ldb, long sB1, long sB2,
             float* __restrict__ C, int ldc, long sC1, long sC2,
             int bdiv, float alpha,
             const float* __restrict__ bias,
             const float* __restrict__ res)
{
    constexpr int TH = (BM/8)*(BN/8);
    int z  = blockIdx.z;
    int z1 = z / bdiv, z2 = z % bdiv;
    A  += (long)z1 * sA1 + (long)z2 * sA2;
    Bp += (long)z1 * sB1 + (long)z2 * sB2;
    long offC = (long)z1 * sC1 + (long)z2 * sC2;
    C += offC;
    const float* R = (EPI == EPI_BIAS_RES) ? (res + offC) : nullptr;

    __shared__ float As[8][BM];
    __shared__ float Bs[8][BN];

    int tid = threadIdx.x;
    int tx  = tid % (BN/8);
    int ty  = tid / (BN/8);
    int row0 = blockIdx.y * BM;
    int col0 = blockIdx.x * BN;

    float acc[8][8];
    #pragma unroll
    for (int i = 0; i < 8; i++)
        #pragma unroll
        for (int j = 0; j < 8; j++) acc[i][j] = 0.f;

    constexpr int LA = BM*8/TH;
    constexpr int LB = BN*8/TH;

    for (int k0 = 0; k0 < K; k0 += 8) {
        #pragma unroll
        for (int i = 0; i < LA; i++) {
            int idx = tid + i*TH;
            int kk = idx & 7, mm = idx >> 3;
            As[kk][mm] = A[(long)(row0+mm)*lda + (k0+kk)];
        }
        #pragma unroll
        for (int i = 0; i < LB; i++) {
            int idx = tid + i*TH;
            if (TB) {
                int kk = idx & 7, nn = idx >> 3;
                Bs[kk][nn] = Bp[(long)(col0+nn)*ldb + (k0+kk)];
            } else {
                int nn = idx % BN, kk = idx / BN;
                Bs[kk][nn] = Bp[(long)(k0+kk)*ldb + (col0+nn)];
            }
        }
        __syncthreads();
        #pragma unroll
        for (int k = 0; k < 8; k++) {
            float a[8], b[8];
            #pragma unroll
            for (int i = 0; i < 4; i++) {
                a[i]   = As[k][ty*4 + i];
                a[i+4] = As[k][BM/2 + ty*4 + i];
                b[i]   = Bs[k][tx*4 + i];
                b[i+4] = Bs[k][BN/2 + tx*4 + i];
            }
            #pragma unroll
            for (int i = 0; i < 8; i++)
                #pragma unroll
                for (int j = 0; j < 8; j++)
                    acc[i][j] += a[i] * b[j];
        }
        __syncthreads();
    }

    #pragma unroll
    for (int i = 0; i < 8; i++) {
        int m = row0 + ((i < 4) ? (ty*4 + i) : (BM/2 + ty*4 + (i-4)));
        #pragma unroll
        for (int j = 0; j < 8; j++) {
            int n = col0 + ((j < 4) ? (tx*4 + j) : (BN/2 + tx*4 + (j-4)));
            float vv = alpha * acc[i][j];
            if (EPI != EPI_NONE)       vv += bias[n];
            if (EPI == EPI_BIAS_GELU)  vv = gelu_f(vv);
            if (EPI == EPI_BIAS_RES)   vv += R[(long)m*ldc + n];
            C[(long)m*ldc + n] = vv;
        }
    }
}

template<int BM,int BN,bool TB,int EPI>
static inline void run_gemm(int M,int N,int K,
    const float* A,int lda,long sA1,long sA2,
    const float* B,int ldb,long sB1,long sB2,
    float* C,int ldc,long sC1,long sC2,
    int batches,int bdiv,float alpha,const float* bias,const float* res)
{
    dim3 grid(N/BN, M/BM, batches);
    sgemm_k<BM,BN,TB,EPI><<<grid, (BM/8)*(BN/8)>>>(
        M,N,K, A,lda,sA1,sA2, B,ldb,sB1,sB2, C,ldc,sC1,sC2,
        bdiv, alpha, bias, res);
}

// ---------------- embedding ----------------
__global__ void embed_k(const int* __restrict__ ids, const float* __restrict__ tok,
                        const float* __restrict__ pos, float* __restrict__ x)
{
    long i = (long)blockIdx.x * blockDim.x + threadIdx.x;
    if (i >= (long)BT * D) return;
    int d  = (int)(i % D);
    int bt = (int)(i / D);
    int t  = bt % T;
    x[i] = tok[(long)ids[bt] * D + d] + pos[(long)t * D + d];
}

// ---------------- row softmax over T=2048 (in place) ----------------
__global__ void softmax_row_k(float* __restrict__ s)
{
    __shared__ float buf[T];
    __shared__ float red[8];
    long base = (long)blockIdx.x * T;
    int tid = threadIdx.x;  // 256
    float m = -FLT_MAX;
    #pragma unroll
    for (int i = 0; i < T/256; i++) {
        float v = s[base + tid + i*256];
        buf[tid + i*256] = v;
        m = fmaxf(m, v);
    }
    #pragma unroll
    for (int o = 16; o > 0; o >>= 1) m = fmaxf(m, __shfl_xor_sync(0xffffffffu, m, o));
    if ((tid & 31) == 0) red[tid >> 5] = m;
    __syncthreads();
    m = red[0];
    #pragma unroll
    for (int i = 1; i < 8; i++) m = fmaxf(m, red[i]);
    float sum = 0.f;
    #pragma unroll
    for (int i = 0; i < T/256; i++) {
        float e = expf(buf[tid + i*256] - m);
        buf[tid + i*256] = e;
        sum += e;
    }
    #pragma unroll
    for (int o = 16; o > 0; o >>= 1) sum += __shfl_xor_sync(0xffffffffu, sum, o);
    __syncthreads();
    if ((tid & 31) == 0) red[tid >> 5] = sum;
    __syncthreads();
    sum = 0.f;
    #pragma unroll
    for (int i = 0; i < 8; i++) sum += red[i];
    float inv = 1.f / sum;
    #pragma unroll
    for (int i = 0; i < T/256; i++)
        s[base + tid + i*256] = buf[tid + i*256] * inv;
}

// ---------------- RMS norm over D=512 (in place) ----------------
__global__ void rmsnorm_k(float* __restrict__ x, const float* __restrict__ w)
{
    int row = blockIdx.x;
    float4* p = (float4*)(x + (long)row * D);
    int tid = threadIdx.x;  // 128
    float4 a = p[tid];
    float ss = a.x*a.x + a.y*a.y + a.z*a.z + a.w*a.w;
    #pragma unroll
    for (int o = 16; o > 0; o >>= 1) ss += __shfl_xor_sync(0xffffffffu, ss, o);
    __shared__ float s4[4];
    if ((tid & 31) == 0) s4[tid >> 5] = ss;
    __syncthreads();
    float tot = s4[0] + s4[1] + s4[2] + s4[3];
    float r = rsqrtf(tot * (1.0f / D) + 1e-8f);
    float4 wv = ((const float4*)w)[tid];
    a.x *= r * wv.x; a.y *= r * wv.y; a.z *= r * wv.z; a.w *= r * wv.w;
    p[tid] = a;
}

// ---------------- top-k over SLOTS + weighted gather of mem_V ----------------
__global__ void topk_read_k(const float* __restrict__ ms,
                            const float* __restrict__ memV,
                            float* __restrict__ outrd)
{
    constexpr int NT = 256;
    int t = blockIdx.x;
    const float* row = ms + (long)t * SLOTS;
    int tid = threadIdx.x;

    // per-thread register top-8 over strided slots (each thread sees 128 values)
    float lv[TOPK]; int li[TOPK];
    #pragma unroll
    for (int i = 0; i < TOPK; i++) { lv[i] = -FLT_MAX; li[i] = 0; }
    for (int j = tid; j < SLOTS; j += NT) {
        float v = row[j];
        if (v > lv[TOPK-1]) {
            float cv = v; int ci = j;
            #pragma unroll
            for (int p = 0; p < TOPK; p++) {
                if (cv > lv[p]) {
                    float tv = lv[p]; int ti = li[p];
                    lv[p] = cv; li[p] = ci; cv = tv; ci = ti;
                }
            }
        }
    }

    __shared__ float sv[NT*TOPK];
    __shared__ int   si[NT*TOPK];
    #pragma unroll
    for (int i = 0; i < TOPK; i++) { sv[tid*TOPK + i] = lv[i]; si[tid*TOPK + i] = li[i]; }
    __syncthreads();

    __shared__ float rv[NT]; __shared__ int rs[NT]; __shared__ int rp[NT];
    __shared__ float bw[TOPK]; __shared__ int bi[TOPK];

    for (int r = 0; r < TOPK; r++) {
        float bv = sv[tid]; int bslot = si[tid]; int bp = tid;
        #pragma unroll
        for (int i = 1; i < TOPK; i++) {
            int p = tid + i*NT;
            float v = sv[p]; int s = si[p];
            if (v > bv || (v == bv && s < bslot)) { bv = v; bslot = s; bp = p; }
        }
        rv[tid] = bv; rs[tid] = bslot; rp[tid] = bp;
        __syncthreads();
        for (int o = NT/2; o > 0; o >>= 1) {
            if (tid < o) {
                float v = rv[tid+o]; int s = rs[tid+o];
                if (v > rv[tid] || (v == rv[tid] && s < rs[tid])) {
                    rv[tid] = v; rs[tid] = s; rp[tid] = rp[tid+o];
                }
            }
            __syncthreads();
        }
        if (tid == 0) { bw[r] = rv[0]; bi[r] = rs[0]; sv[rp[0]] = -FLT_MAX; }
        __syncthreads();
    }

    __shared__ float w8[TOPK];
    if (tid == 0) {
        float mx = bw[0];           // rounds pick descending maxima
        float e[TOPK]; float s = 0.f;
        #pragma unroll
        for (int k = 0; k < TOPK; k++) { e[k] = expf(bw[k] - mx); s += e[k]; }
        float inv = 1.f / s;
        #pragma unroll
        for (int k = 0; k < TOPK; k++) w8[k] = e[k] * inv;
    }
    __syncthreads();

    for (int d = tid; d < D; d += NT) {
        float acc = 0.f;
        #pragma unroll
        for (int k = 0; k < TOPK; k++)
            acc += w8[k] * memV[(long)bi[k]*D + d];
        outrd[(long)t*D + d] = acc;
    }
}

// ---------------- launcher ----------------
extern "C" void kernel_launch(void* const* d_in, const int* in_sizes, int n_in,
                              void* d_out, int out_size)
{
    (void)in_sizes; (void)n_in; (void)out_size;
    const int*   ids  = (const int*)  d_in[0];
    const float* tok  = (const float*)d_in[1];
    const float* pos  = (const float*)d_in[2];
    const float* wq   = (const float*)d_in[3];
    const float* wk   = (const float*)d_in[4];
    const float* wv   = (const float*)d_in[5];
    const float* wo   = (const float*)d_in[6];
    const float* bo   = (const float*)d_in[7];
    const float* n1   = (const float*)d_in[8];
    const float* fw1  = (const float*)d_in[9];
    const float* fb1  = (const float*)d_in[10];
    const float* fw2  = (const float*)d_in[11];
    const float* fb2  = (const float*)d_in[12];
    const float* n2   = (const float*)d_in[13];
    const float* memK = (const float*)d_in[14];
    const float* memV = (const float*)d_in[15];
    const float* sal  = (const float*)d_in[16];
    const float* wqm  = (const float*)d_in[17];
    const float* bqm  = (const float*)d_in[18];
    const float* wrd  = (const float*)d_in[19];
    const float* brd  = (const float*)d_in[20];
    const float* nout = (const float*)d_in[21];
    float* out = (float*)d_out;

    float* S = nullptr;
    cudaGetSymbolAddress((void**)&S, g_scratch);
    float* x    = S + OFF_X;
    float* q    = S + OFF_Q;
    float* kbuf = S + OFF_K;
    float* vbuf = S + OFF_V;
    float* ao   = S + OFF_AO;
    float* mq   = S + OFF_MQ;
    float* rd   = S + OFF_RD;
    float* hh   = S + OFF_HH;
    float* sc   = S + OFF_SC;
    float* msc  = S + OFF_MS;

    // x = tok_embed[ids] + pos_embed[:T]
    embed_k<<<(int)(((long)BT*D + 255) / 256), 256>>>(ids, tok, pos, x);

    const float inv_sqrt_dh = 0.125f;                 // 64^-0.5
    const float inv_sqrt_d  = 1.0f / sqrtf((float)D); // 512^-0.5

    for (int l = 0; l < NL; l++) {
        const float* Wq = wq + (long)l*D*D;
        const float* Wk = wk + (long)l*D*D;
        const float* Wv = wv + (long)l*D*D;

        run_gemm<128,128,false,EPI_NONE>(BT, D, D, x, D,0,0, Wq, D,0,0, q,    D,0,0, 1,1, 1.f, nullptr, nullptr);
        run_gemm<128,128,false,EPI_NONE>(BT, D, D, x, D,0,0, Wk, D,0,0, kbuf, D,0,0, 1,1, 1.f, nullptr, nullptr);
        run_gemm<128,128,false,EPI_NONE>(BT, D, D, x, D,0,0, Wv, D,0,0, vbuf, D,0,0, 1,1, 1.f, nullptr, nullptr);

        // scores[b,h,i,j] = (q_i . k_j) * dh^-0.5   (batched over 16 (b,h))
        run_gemm<128,128,true,EPI_NONE>(T, T, DH,
            q,    D, (long)T*D, DH,
            kbuf, D, (long)T*D, DH,
            sc,   T, (long)H*T*T, (long)T*T,
            BATCH*H, H, inv_sqrt_dh, nullptr, nullptr);

        softmax_row_k<<<BATCH*H*T, 256>>>(sc);

        // ao = attn @ v  (batched, written head-interleaved into [BT,D])
        run_gemm<128,64,false,EPI_NONE>(T, DH, T,
            sc,   T, (long)H*T*T, (long)T*T,
            vbuf, D, (long)T*D, DH,
            ao,   D, (long)T*D, DH,
            BATCH*H, H, 1.f, nullptr, nullptr);

        // x = x + ao @ wo + bo ; rms(norm1)
        run_gemm<128,128,false,EPI_BIAS_RES>(BT, D, D, ao, D,0,0, wo + (long)l*D*D, D,0,0,
                                             x, D,0,0, 1,1, 1.f, bo + (long)l*D, x);
        rmsnorm_k<<<BT, 128>>>(x, n1 + (long)l*D);

        // h = gelu(x @ ffw1 + b1) ; x = x + h @ ffw2 + b2 ; rms(norm2)
        run_gemm<128,128,false,EPI_BIAS_GELU>(BT, FF, D, x, D,0,0, fw1 + (long)l*D*FF, FF,0,0,
                                              hh, FF,0,0, 1,1, 1.f, fb1 + (long)l*FF, nullptr);
        run_gemm<128,128,false,EPI_BIAS_RES>(BT, D, FF, hh, FF,0,0, fw2 + (long)l*FF*D, D,0,0,
                                             x, D,0,0, 1,1, 1.f, fb2 + (long)l*D, x);
        rmsnorm_k<<<BT, 128>>>(x, n2 + (long)l*D);
    }

    // memory read
    run_gemm<128,128,false,EPI_BIAS>(BT, D, D, x, D,0,0, wqm, D,0,0, mq, D,0,0, 1,1, 1.f, bqm, nullptr);
    // mscores = mq @ mem_K^T * D^-0.5 + salience
    run_gemm<128,128,true,EPI_BIAS>(BT, SLOTS, D, mq, D,0,0, memK, D,0,0,
                                    msc, SLOTS,0,0, 1,1, inv_sqrt_d, sal, nullptr);
    topk_read_k<<<BT, 256>>>(msc, memV, rd);
    // x = x + read @ w_read + b_read ; rms(norm_out)
    run_gemm<128,128,false,EPI_BIAS_RES>(BT, D, D, rd, D,0,0, wrd, D,0,0,
                                         x, D,0,0, 1,1, 1.f, brd, x);
    rmsnorm_k<<<BT, 128>>>(x, nout);

    // logits = x @ tok_embed^T
    run_gemm<128,128,true,EPI_NONE>(BT, V, D, x, D,0,0, tok, D,0,0,
                                    out, V,0,0, 1,1, 1.f, nullptr, nullptr);
}

// round 13
// speedup vs baseline: 1.5102x; 1.5102x over previous
#include <cuda_runtime.h>
#include <math.h>
#include <float.h>

static constexpr int BATCH = 2;
static constexpr int T     = 2048;
static constexpr int BT    = BATCH * T;      // 4096
static constexpr int D     = 512;
static constexpr int H     = 8;
static constexpr int DH    = 64;
static constexpr int NL    = 4;
static constexpr int FF    = 2048;
static constexpr int V     = 32000;
static constexpr int SLOTS = 32768;
static constexpr int TOPK  = 8;

// ---------------- scratch (single __device__ array, carved by offsets) ----------------
static constexpr long OFF_X  = 0;
static constexpr long OFF_Q  = OFF_X  + (long)BT * D;
static constexpr long OFF_K  = OFF_Q  + (long)BT * D;
static constexpr long OFF_V  = OFF_K  + (long)BT * D;
static constexpr long OFF_AO = OFF_V  + (long)BT * D;
static constexpr long OFF_MQ = OFF_AO + (long)BT * D;
static constexpr long OFF_RD = OFF_MQ + (long)BT * D;
static constexpr long OFF_HH = OFF_RD + (long)BT * D;
static constexpr long OFF_SC = OFF_HH + (long)BT * FF;
static constexpr long OFF_MS = OFF_SC + (long)BATCH * H * T * T;
static constexpr long SCRATCH_TOTAL = OFF_MS + (long)BT * SLOTS;

__device__ float g_scratch[SCRATCH_TOTAL];

__device__ __forceinline__ float gelu_f(float x) {
    float x3 = x * x * x;
    return 0.5f * x * (1.0f + tanhf(0.7978845608028654f * (x + 0.044715f * x3)));
}

enum { EPI_NONE = 0, EPI_BIAS = 1, EPI_BIAS_RES = 2, EPI_BIAS_GELU = 3 };

// ---------------- tiled SGEMM with packed f32x2 FMA + double-buffered smem ----------------
// C[M,N] = alpha * A[M,K] @ op(B) (+bias[n]) (+gelu) (+res), op(B)=B^T when TB
// Batched via blockIdx.z. REQUIRES: M%BM==0, N%BN==0, K%8==0, all leading dims %4==0.
template<int BM, int BN, bool TB, int EPI>
__global__ __launch_bounds__((BM/8)*(BN/8), 2)
void sgemm_k(int M, int N, int K,
             const float* __restrict__ A, int lda, long sA1, long sA2,
             const float* __restrict__ Bp, int ldb, long sB1, long sB2,
             float* __restrict__ C, int ldc, long sC1, long sC2,
             int bdiv, float alpha,
             const float* __restrict__ bias,
             const float* __restrict__ res)
{
    constexpr int TH  = (BM/8)*(BN/8);
    constexpr int CA  = (BM*2)/TH;   // float4 chunks of the BMx8 A tile per thread
    constexpr int CB  = (BN*2)/TH;   // float4 chunks of the 8xBN (or BNx8) B tile per thread
    constexpr int BMP = BM + 4;
    constexpr int BNP = BN + 4;

    int z  = blockIdx.z;
    int z1 = z / bdiv, z2 = z % bdiv;
    A  += (long)z1 * sA1 + (long)z2 * sA2;
    Bp += (long)z1 * sB1 + (long)z2 * sB2;
    long offC = (long)z1 * sC1 + (long)z2 * sC2;
    C += offC;
    const float* R = (EPI == EPI_BIAS_RES) ? (res + offC) : nullptr;

    __shared__ float As[2][8][BMP];
    __shared__ float Bs[2][8][BNP];

    int tid  = threadIdx.x;
    int tx   = tid % (BN/8);
    int ty   = tid / (BN/8);
    int row0 = blockIdx.y * BM;
    int col0 = blockIdx.x * BN;

    unsigned long long acc2[8][4];   // each packs two fp32 accumulators (f32x2)
    #pragma unroll
    for (int i = 0; i < 8; i++)
        #pragma unroll
        for (int j = 0; j < 4; j++) acc2[i][j] = 0ull;

    float4 pa[CA], pb[CB];

    auto load_regs = [&](int k0) {
        #pragma unroll
        for (int c = 0; c < CA; c++) {
            int g = tid + c*TH;
            int mm = g >> 1, half = g & 1;
            pa[c] = *reinterpret_cast<const float4*>(&A[(long)(row0+mm)*lda + k0 + half*4]);
        }
        #pragma unroll
        for (int c = 0; c < CB; c++) {
            int g = tid + c*TH;
            if (TB) {
                int nn = g >> 1, half = g & 1;
                pb[c] = *reinterpret_cast<const float4*>(&Bp[(long)(col0+nn)*ldb + k0 + half*4]);
            } else {
                int kk = g / (BN/4), cc = g % (BN/4);
                pb[c] = *reinterpret_cast<const float4*>(&Bp[(long)(k0+kk)*ldb + col0 + cc*4]);
            }
        }
    };

    auto store_smem = [&](int buf) {
        #pragma unroll
        for (int c = 0; c < CA; c++) {
            int g = tid + c*TH;
            int mm = g >> 1, half = g & 1;
            As[buf][half*4+0][mm] = pa[c].x;
            As[buf][half*4+1][mm] = pa[c].y;
            As[buf][half*4+2][mm] = pa[c].z;
            As[buf][half*4+3][mm] = pa[c].w;
        }
        #pragma unroll
        for (int c = 0; c < CB; c++) {
            int g = tid + c*TH;
            if (TB) {
                int nn = g >> 1, half = g & 1;
                Bs[buf][half*4+0][nn] = pb[c].x;
                Bs[buf][half*4+1][nn] = pb[c].y;
                Bs[buf][half*4+2][nn] = pb[c].z;
                Bs[buf][half*4+3][nn] = pb[c].w;
            } else {
                int kk = g / (BN/4), cc = g % (BN/4);
                *reinterpret_cast<float4*>(&Bs[buf][kk][cc*4]) = pb[c];
            }
        }
    };

    load_regs(0);
    store_smem(0);
    __syncthreads();

    int nbuf = K / 8;
    for (int it = 0; it < nbuf; it++) {
        int cur = it & 1;
        bool more = (it + 1 < nbuf);
        if (more) load_regs((it + 1) * 8);

        #pragma unroll
        for (int k = 0; k < 8; k++) {
            float4 av0 = *reinterpret_cast<const float4*>(&As[cur][k][ty*4]);
            float4 av1 = *reinterpret_cast<const float4*>(&As[cur][k][BM/2 + ty*4]);
            const unsigned long long* bp0 =
                reinterpret_cast<const unsigned long long*>(&Bs[cur][k][tx*4]);
            const unsigned long long* bp1 =
                reinterpret_cast<const unsigned long long*>(&Bs[cur][k][BN/2 + tx*4]);
            unsigned long long b2[4];
            b2[0] = bp0[0]; b2[1] = bp0[1]; b2[2] = bp1[0]; b2[3] = bp1[1];
            float af[8] = {av0.x, av0.y, av0.z, av0.w, av1.x, av1.y, av1.z, av1.w};
            #pragma unroll
            for (int i = 0; i < 8; i++) {
                unsigned long long a2;
                asm("mov.b64 %0, {%1, %1};" : "=l"(a2) : "f"(af[i]));
                #pragma unroll
                for (int j = 0; j < 4; j++)
                    asm("fma.rn.f32x2 %0, %1, %2, %3;"
                        : "=l"(acc2[i][j]) : "l"(a2), "l"(b2[j]), "l"(acc2[i][j]));
            }
        }

        if (more) store_smem(cur ^ 1);
        __syncthreads();
    }

    // epilogue (float4 stores; columns tx*4..tx*4+3 and BN/2+tx*4..+3 are contiguous)
    int n0 = col0 + tx*4;
    int n1 = col0 + BN/2 + tx*4;
    float4 bia0 = make_float4(0.f,0.f,0.f,0.f), bia1 = bia0;
    if (EPI != EPI_NONE) {
        bia0 = *reinterpret_cast<const float4*>(&bias[n0]);
        bia1 = *reinterpret_cast<const float4*>(&bias[n1]);
    }
    #pragma unroll
    for (int i = 0; i < 8; i++) {
        int m = row0 + ((i < 4) ? (ty*4 + i) : (BM/2 + ty*4 + (i-4)));
        float cf[8];
        #pragma unroll
        for (int j = 0; j < 4; j++) {
            float2 p = *reinterpret_cast<float2*>(&acc2[i][j]);
            cf[2*j]   = p.x;
            cf[2*j+1] = p.y;
        }
        float4 v0 = make_float4(alpha*cf[0], alpha*cf[1], alpha*cf[2], alpha*cf[3]);
        float4 v1 = make_float4(alpha*cf[4], alpha*cf[5], alpha*cf[6], alpha*cf[7]);
        if (EPI != EPI_NONE) {
            v0.x += bia0.x; v0.y += bia0.y; v0.z += bia0.z; v0.w += bia0.w;
            v1.x += bia1.x; v1.y += bia1.y; v1.z += bia1.z; v1.w += bia1.w;
        }
        if (EPI == EPI_BIAS_GELU) {
            v0.x = gelu_f(v0.x); v0.y = gelu_f(v0.y); v0.z = gelu_f(v0.z); v0.w = gelu_f(v0.w);
            v1.x = gelu_f(v1.x); v1.y = gelu_f(v1.y); v1.z = gelu_f(v1.z); v1.w = gelu_f(v1.w);
        }
        if (EPI == EPI_BIAS_RES) {
            float4 r0 = *reinterpret_cast<const float4*>(&R[(long)m*ldc + n0]);
            float4 r1 = *reinterpret_cast<const float4*>(&R[(long)m*ldc + n1]);
            v0.x += r0.x; v0.y += r0.y; v0.z += r0.z; v0.w += r0.w;
            v1.x += r1.x; v1.y += r1.y; v1.z += r1.z; v1.w += r1.w;
        }
        *reinterpret_cast<float4*>(&C[(long)m*ldc + n0]) = v0;
        *reinterpret_cast<float4*>(&C[(long)m*ldc + n1]) = v1;
    }
}

template<int BM,int BN,bool TB,int EPI>
static inline void run_gemm(int M,int N,int K,
    const float* A,int lda,long sA1,long sA2,
    const float* B,int ldb,long sB1,long sB2,
    float* C,int ldc,long sC1,long sC2,
    int batches,int bdiv,float alpha,const float* bias,const float* res)
{
    dim3 grid(N/BN, M/BM, batches);
    sgemm_k<BM,BN,TB,EPI><<<grid, (BM/8)*(BN/8)>>>(
        M,N,K, A,lda,sA1,sA2, B,ldb,sB1,sB2, C,ldc,sC1,sC2,
        bdiv, alpha, bias, res);
}

// ---------------- embedding ----------------
__global__ void embed_k(const int* __restrict__ ids, const float* __restrict__ tok,
                        const float* __restrict__ pos, float* __restrict__ x)
{
    long i = (long)blockIdx.x * blockDim.x + threadIdx.x;
    if (i >= (long)BT * D) return;
    int d  = (int)(i % D);
    int bt = (int)(i / D);
    int t  = bt % T;
    x[i] = tok[(long)ids[bt] * D + d] + pos[(long)t * D + d];
}

// ---------------- row softmax over T=2048 (in place) ----------------
__global__ void softmax_row_k(float* __restrict__ s)
{
    __shared__ float buf[T];
    __shared__ float red[8];
    long base = (long)blockIdx.x * T;
    int tid = threadIdx.x;  // 256
    float m = -FLT_MAX;
    #pragma unroll
    for (int i = 0; i < T/256; i++) {
        float v = s[base + tid + i*256];
        buf[tid + i*256] = v;
        m = fmaxf(m, v);
    }
    #pragma unroll
    for (int o = 16; o > 0; o >>= 1) m = fmaxf(m, __shfl_xor_sync(0xffffffffu, m, o));
    if ((tid & 31) == 0) red[tid >> 5] = m;
    __syncthreads();
    m = red[0];
    #pragma unroll
    for (int i = 1; i < 8; i++) m = fmaxf(m, red[i]);
    float sum = 0.f;
    #pragma unroll
    for (int i = 0; i < T/256; i++) {
        float e = expf(buf[tid + i*256] - m);
        buf[tid + i*256] = e;
        sum += e;
    }
    #pragma unroll
    for (int o = 16; o > 0; o >>= 1) sum += __shfl_xor_sync(0xffffffffu, sum, o);
    __syncthreads();
    if ((tid & 31) == 0) red[tid >> 5] = sum;
    __syncthreads();
    sum = 0.f;
    #pragma unroll
    for (int i = 0; i < 8; i++) sum += red[i];
    float inv = 1.f / sum;
    #pragma unroll
    for (int i = 0; i < T/256; i++)
        s[base + tid + i*256] = buf[tid + i*256] * inv;
}

// ---------------- RMS norm over D=512 (in place) ----------------
__global__ void rmsnorm_k(float* __restrict__ x, const float* __restrict__ w)
{
    int row = blockIdx.x;
    float4* p = (float4*)(x + (long)row * D);
    int tid = threadIdx.x;  // 128
    float4 a = p[tid];
    float ss = a.x*a.x + a.y*a.y + a.z*a.z + a.w*a.w;
    #pragma unroll
    for (int o = 16; o > 0; o >>= 1) ss += __shfl_xor_sync(0xffffffffu, ss, o);
    __shared__ float s4[4];
    if ((tid & 31) == 0) s4[tid >> 5] = ss;
    __syncthreads();
    float tot = s4[0] + s4[1] + s4[2] + s4[3];
    float r = rsqrtf(tot * (1.0f / D) + 1e-8f);
    float4 wv = ((const float4*)w)[tid];
    a.x *= r * wv.x; a.y *= r * wv.y; a.z *= r * wv.z; a.w *= r * wv.w;
    p[tid] = a;
}

// ---------------- top-k over SLOTS + weighted gather of mem_V ----------------
__global__ void topk_read_k(const float* __restrict__ ms,
                            const float* __restrict__ memV,
                            float* __restrict__ outrd)
{
    constexpr int NT = 256;
    int t = blockIdx.x;
    const float* row = ms + (long)t * SLOTS;
    int tid = threadIdx.x;

    float lv[TOPK]; int li[TOPK];
    #pragma unroll
    for (int i = 0; i < TOPK; i++) { lv[i] = -FLT_MAX; li[i] = 0; }
    for (int j = tid; j < SLOTS; j += NT) {
        float v = row[j];
        if (v > lv[TOPK-1]) {
            float cv = v; int ci = j;
            #pragma unroll
            for (int p = 0; p < TOPK; p++) {
                if (cv > lv[p]) {
                    float tv = lv[p]; int ti = li[p];
                    lv[p] = cv; li[p] = ci; cv = tv; ci = ti;
                }
            }
        }
    }

    __shared__ float sv[NT*TOPK];
    __shared__ int   si[NT*TOPK];
    #pragma unroll
    for (int i = 0; i < TOPK; i++) { sv[tid*TOPK + i] = lv[i]; si[tid*TOPK + i] = li[i]; }
    __syncthreads();

    __shared__ float rv[NT]; __shared__ int rs[NT]; __shared__ int rp[NT];
    __shared__ float bw[TOPK]; __shared__ int bi[TOPK];

    for (int r = 0; r < TOPK; r++) {
        float bv = sv[tid]; int bslot = si[tid]; int bp = tid;
        #pragma unroll
        for (int i = 1; i < TOPK; i++) {
            int p = tid + i*NT;
            float v = sv[p]; int s = si[p];
            if (v > bv || (v == bv && s < bslot)) { bv = v; bslot = s; bp = p; }
        }
        rv[tid] = bv; rs[tid] = bslot; rp[tid] = bp;
        __syncthreads();
        for (int o = NT/2; o > 0; o >>= 1) {
            if (tid < o) {
                float v = rv[tid+o]; int s = rs[tid+o];
                if (v > rv[tid] || (v == rv[tid] && s < rs[tid])) {
                    rv[tid] = v; rs[tid] = s; rp[tid] = rp[tid+o];
                }
            }
            __syncthreads();
        }
        if (tid == 0) { bw[r] = rv[0]; bi[r] = rs[0]; sv[rp[0]] = -FLT_MAX; }
        __syncthreads();
    }

    __shared__ float w8[TOPK];
    if (tid == 0) {
        float mx = bw[0];
        float e[TOPK]; float s = 0.f;
        #pragma unroll
        for (int k = 0; k < TOPK; k++) { e[k] = expf(bw[k] - mx); s += e[k]; }
        float inv = 1.f / s;
        #pragma unroll
        for (int k = 0; k < TOPK; k++) w8[k] = e[k] * inv;
    }
    __syncthreads();

    for (int d = tid; d < D; d += NT) {
        float acc = 0.f;
        #pragma unroll
        for (int k = 0; k < TOPK; k++)
            acc += w8[k] * memV[(long)bi[k]*D + d];
        outrd[(long)t*D + d] = acc;
    }
}

// ---------------- launcher ----------------
extern "C" void kernel_launch(void* const* d_in, const int* in_sizes, int n_in,
                              void* d_out, int out_size)
{
    (void)in_sizes; (void)n_in; (void)out_size;
    const int*   ids  = (const int*)  d_in[0];
    const float* tok  = (const float*)d_in[1];
    const float* pos  = (const float*)d_in[2];
    const float* wq   = (const float*)d_in[3];
    const float* wk   = (const float*)d_in[4];
    const float* wv   = (const float*)d_in[5];
    const float* wo   = (const float*)d_in[6];
    const float* bo   = (const float*)d_in[7];
    const float* n1   = (const float*)d_in[8];
    const float* fw1  = (const float*)d_in[9];
    const float* fb1  = (const float*)d_in[10];
    const float* fw2  = (const float*)d_in[11];
    const float* fb2  = (const float*)d_in[12];
    const float* n2   = (const float*)d_in[13];
    const float* memK = (const float*)d_in[14];
    const float* memV = (const float*)d_in[15];
    const float* sal  = (const float*)d_in[16];
    const float* wqm  = (const float*)d_in[17];
    const float* bqm  = (const float*)d_in[18];
    const float* wrd  = (const float*)d_in[19];
    const float* brd  = (const float*)d_in[20];
    const float* nout = (const float*)d_in[21];
    float* out = (float*)d_out;

    float* S = nullptr;
    cudaGetSymbolAddress((void**)&S, g_scratch);
    float* x    = S + OFF_X;
    float* q    = S + OFF_Q;
    float* kbuf = S + OFF_K;
    float* vbuf = S + OFF_V;
    float* ao   = S + OFF_AO;
    float* mq   = S + OFF_MQ;
    float* rd   = S + OFF_RD;
    float* hh   = S + OFF_HH;
    float* sc   = S + OFF_SC;
    float* msc  = S + OFF_MS;

    embed_k<<<(int)(((long)BT*D + 255) / 256), 256>>>(ids, tok, pos, x);

    const float inv_sqrt_dh = 0.125f;
    const float inv_sqrt_d  = 1.0f / sqrtf((float)D);

    for (int l = 0; l < NL; l++) {
        const float* Wq = wq + (long)l*D*D;
        const float* Wk = wk + (long)l*D*D;
        const float* Wv = wv + (long)l*D*D;

        run_gemm<128,128,false,EPI_NONE>(BT, D, D, x, D,0,0, Wq, D,0,0, q,    D,0,0, 1,1, 1.f, nullptr, nullptr);
        run_gemm<128,128,false,EPI_NONE>(BT, D, D, x, D,0,0, Wk, D,0,0, kbuf, D,0,0, 1,1, 1.f, nullptr, nullptr);
        run_gemm<128,128,false,EPI_NONE>(BT, D, D, x, D,0,0, Wv, D,0,0, vbuf, D,0,0, 1,1, 1.f, nullptr, nullptr);

        run_gemm<128,128,true,EPI_NONE>(T, T, DH,
            q,    D, (long)T*D, DH,
            kbuf, D, (long)T*D, DH,
            sc,   T, (long)H*T*T, (long)T*T,
            BATCH*H, H, inv_sqrt_dh, nullptr, nullptr);

        softmax_row_k<<<BATCH*H*T, 256>>>(sc);

        run_gemm<128,64,false,EPI_NONE>(T, DH, T,
            sc,   T, (long)H*T*T, (long)T*T,
            vbuf, D, (long)T*D, DH,
            ao,   D, (long)T*D, DH,
            BATCH*H, H, 1.f, nullptr, nullptr);

        run_gemm<128,128,false,EPI_BIAS_RES>(BT, D, D, ao, D,0,0, wo + (long)l*D*D, D,0,0,
                                             x, D,0,0, 1,1, 1.f, bo + (long)l*D, x);
        rmsnorm_k<<<BT, 128>>>(x, n1 + (long)l*D);

        run_gemm<128,128,false,EPI_BIAS_GELU>(BT, FF, D, x, D,0,0, fw1 + (long)l*D*FF, FF,0,0,
                                              hh, FF,0,0, 1,1, 1.f, fb1 + (long)l*FF, nullptr);
        run_gemm<128,128,false,EPI_BIAS_RES>(BT, D, FF, hh, FF,0,0, fw2 + (long)l*FF*D, D,0,0,
                                             x, D,0,0, 1,1, 1.f, fb2 + (long)l*D, x);
        rmsnorm_k<<<BT, 128>>>(x, n2 + (long)l*D);
    }

    run_gemm<128,128,false,EPI_BIAS>(BT, D, D, x, D,0,0, wqm, D,0,0, mq, D,0,0, 1,1, 1.f, bqm, nullptr);
    run_gemm<128,128,true,EPI_BIAS>(BT, SLOTS, D, mq, D,0,0, memK, D,0,0,
                                    msc, SLOTS,0,0, 1,1, inv_sqrt_d, sal, nullptr);
    topk_read_k<<<BT, 256>>>(msc, memV, rd);
    run_gemm<128,128,false,EPI_BIAS_RES>(BT, D, D, rd, D,0,0, wrd, D,0,0,
                                         x, D,0,0, 1,1, 1.f, brd, x);
    rmsnorm_k<<<BT, 128>>>(x, nout);

    run_gemm<128,128,true,EPI_NONE>(BT, V, D, x, D,0,0, tok, D,0,0,
                                    out, V,0,0, 1,1, 1.f, nullptr, nullptr);
}